// round 1
// baseline (speedup 1.0000x reference)
#include <cuda_runtime.h>
#include <math.h>

#define EPS_LN 1e-5f

static constexpr int BB    = 2048;
static constexpr int KK    = 8;
static constexpr int BKTOT = BB * KK;          // 16384
static constexpr int RR    = BKTOT * (KK - 1); // 114688
static constexpr int HH    = 250;
static constexpr int MX    = 576;
static constexpr int HAH   = 100;
static constexpr int KOUT  = HH + HH + MX;     // 1076

// Scratch (device globals: allocation-free per harness rules)
__device__ float g_s1  [BKTOT * HH];
__device__ float g_core[RR * HH];
__device__ float g_ctx [RR * HH];
__device__ float g_att [RR];
__device__ float g_eff [BKTOT * HH];

// GATHER: 0 = plain row-major A; 1 = pairwise concat gather from s1; 2 = [s1|eff|x] gather
// EPI:    0 = bias only; 1 = relu + LN; 2 = tanh + LN + dot(W2) + sigmoid -> scalar per row
template<int BM, int BN, int BKt, int TM, int TN, int GATHER, int EPI>
__global__ void gemm_fused(
    const float* __restrict__ A,
    const float* __restrict__ A2,
    const float* __restrict__ A3,
    const float* __restrict__ W,
    const float* __restrict__ bias,
    const float* __restrict__ gamma,
    const float* __restrict__ beta,
    const float* __restrict__ W2,
    const float* __restrict__ b2,
    float* __restrict__ Cout,
    int Mrows, int Kdim, int N)
{
    constexpr int NT = (BM / TM) * (BN / TN);
    __shared__ float As[BKt][BM];
    __shared__ float Bs[BKt][BN];
    __shared__ float rsum[BM];
    __shared__ float rsq[BM];

    const int row0  = blockIdx.x * BM;
    const int tid   = threadIdx.x;
    const int tx    = tid % (BN / TN);
    const int ty    = tid / (BN / TN);
    const int trow0 = ty * TM;
    const int tcol0 = tx * TN;

    float acc[TM][TN];
#pragma unroll
    for (int m = 0; m < TM; m++)
#pragma unroll
        for (int n = 0; n < TN; n++) acc[m][n] = 0.f;

    for (int kt = 0; kt < Kdim; kt += BKt) {
        // Load A tile (with optional gather), store transposed
        for (int idx = tid; idx < BM * BKt; idx += NT) {
            int r = idx / BKt, k = idx - r * BKt;
            int gr = row0 + r, gk = kt + k;
            float v = 0.f;
            if (gr < Mrows && gk < Kdim) {
                if (GATHER == 0) {
                    v = A[(size_t)gr * Kdim + gk];
                } else if (GATHER == 1) {
                    int b   = gr / 56;
                    int rem = gr - b * 56;
                    int i   = rem / 7;
                    int jj  = rem - i * 7;
                    int j   = jj + (jj >= i ? 1 : 0);
                    v = (gk < HH) ? A[(size_t)(b * KK + i) * HH + gk]
                                  : A[(size_t)(b * KK + j) * HH + (gk - HH)];
                } else { // GATHER == 2: total = [s1 | eff | x]
                    if (gk < HH)          v = A [(size_t)gr * HH + gk];
                    else if (gk < 2 * HH) v = A2[(size_t)gr * HH + (gk - HH)];
                    else                  v = A3[(size_t)gr * MX + (gk - 2 * HH)];
                }
            }
            As[k][r] = v;
        }
        // Load B tile
        for (int idx = tid; idx < BKt * BN; idx += NT) {
            int k = idx / BN, c = idx - k * BN;
            int gk = kt + k;
            Bs[k][c] = (gk < Kdim && c < N) ? W[(size_t)gk * N + c] : 0.f;
        }
        __syncthreads();

#pragma unroll
        for (int k = 0; k < BKt; k++) {
            float af[TM], bf[TN];
#pragma unroll
            for (int m = 0; m < TM; m++) af[m] = As[k][trow0 + m];
#pragma unroll
            for (int n = 0; n < TN; n++) bf[n] = Bs[k][tcol0 + n];
#pragma unroll
            for (int m = 0; m < TM; m++)
#pragma unroll
                for (int n = 0; n < TN; n++)
                    acc[m][n] = fmaf(af[m], bf[n], acc[m][n]);
        }
        __syncthreads();
    }

    // bias + activation
#pragma unroll
    for (int m = 0; m < TM; m++)
#pragma unroll
        for (int n = 0; n < TN; n++) {
            int c = tcol0 + n;
            float v = acc[m][n] + ((c < N) ? bias[c] : 0.f);
            if (EPI == 1) v = fmaxf(v, 0.f);
            if (EPI == 2) v = tanhf(v);
            acc[m][n] = v;
        }

    if (EPI == 0) {
#pragma unroll
        for (int m = 0; m < TM; m++) {
            int gr = row0 + trow0 + m;
            if (gr >= Mrows) continue;
#pragma unroll
            for (int n = 0; n < TN; n++) {
                int c = tcol0 + n;
                if (c < N) Cout[(size_t)gr * N + c] = acc[m][n];
            }
        }
        return;
    }

    // LayerNorm stats over the N valid columns (entire row lives in this block)
    if (tid < BM) { rsum[tid] = 0.f; rsq[tid] = 0.f; }
    __syncthreads();
#pragma unroll
    for (int m = 0; m < TM; m++) {
        float s = 0.f, q = 0.f;
#pragma unroll
        for (int n = 0; n < TN; n++) {
            int c = tcol0 + n;
            if (c < N) { float v = acc[m][n]; s += v; q += v * v; }
        }
        atomicAdd(&rsum[trow0 + m], s);
        atomicAdd(&rsq [trow0 + m], q);
    }
    __syncthreads();

    float mean[TM], rstd[TM];
#pragma unroll
    for (int m = 0; m < TM; m++) {
        float mu  = rsum[trow0 + m] / (float)N;
        float var = rsq [trow0 + m] / (float)N - mu * mu;
        mean[m] = mu;
        rstd[m] = rsqrtf(var + EPS_LN);
    }

    if (EPI == 1) {
#pragma unroll
        for (int m = 0; m < TM; m++) {
            int gr = row0 + trow0 + m;
            if (gr >= Mrows) continue;
#pragma unroll
            for (int n = 0; n < TN; n++) {
                int c = tcol0 + n;
                if (c < N)
                    Cout[(size_t)gr * N + c] =
                        (acc[m][n] - mean[m]) * rstd[m] * gamma[c] + beta[c];
            }
        }
    } else { // EPI == 2: attention head -> scalar per row
        __syncthreads();
        if (tid < BM) rsum[tid] = 0.f;
        __syncthreads();
#pragma unroll
        for (int m = 0; m < TM; m++) {
            float d = 0.f;
#pragma unroll
            for (int n = 0; n < TN; n++) {
                int c = tcol0 + n;
                if (c < N) {
                    float v = (acc[m][n] - mean[m]) * rstd[m] * gamma[c] + beta[c];
                    d = fmaf(v, W2[c], d);
                }
            }
            atomicAdd(&rsum[trow0 + m], d);
        }
        __syncthreads();
        if (tid < BM) {
            int gr = row0 + tid;
            if (gr < Mrows) {
                float z = rsum[tid] + b2[0];
                Cout[gr] = 1.f / (1.f + expf(-z));
            }
        }
    }
}

// effect[bk, c] = sum_{jj<7} ctx[(bk*7+jj)*250 + c] * att[bk*7+jj]
__global__ void effect_kernel(const float* __restrict__ ctx,
                              const float* __restrict__ att,
                              float* __restrict__ eff)
{
    int bk = blockIdx.x;
    __shared__ float a[7];
    if (threadIdx.x < 7) a[threadIdx.x] = att[bk * 7 + threadIdx.x];
    __syncthreads();
    for (int c = threadIdx.x; c < HH; c += blockDim.x) {
        const float* p = ctx + (size_t)bk * 7 * HH + c;
        float s = 0.f;
#pragma unroll
        for (int jj = 0; jj < 7; jj++) s = fmaf(p[jj * HH], a[jj], s);
        eff[(size_t)bk * HH + c] = s;
    }
}

extern "C" void kernel_launch(void* const* d_in, const int* in_sizes, int n_in,
                              void* d_out, int out_size)
{
    const float* x       = (const float*)d_in[0];
    const float* state   = (const float*)d_in[1];
    const float* enc_W   = (const float*)d_in[2];
    const float* enc_b   = (const float*)d_in[3];
    const float* enc_g   = (const float*)d_in[4];
    const float* enc_bt  = (const float*)d_in[5];
    const float* core_W  = (const float*)d_in[6];
    const float* core_b  = (const float*)d_in[7];
    const float* core_g  = (const float*)d_in[8];
    const float* core_bt = (const float*)d_in[9];
    const float* ctx_W   = (const float*)d_in[10];
    const float* ctx_b   = (const float*)d_in[11];
    const float* ctx_g   = (const float*)d_in[12];
    const float* ctx_bt  = (const float*)d_in[13];
    const float* att_W1  = (const float*)d_in[14];
    const float* att_b1  = (const float*)d_in[15];
    const float* att_g   = (const float*)d_in[16];
    const float* att_bt  = (const float*)d_in[17];
    const float* att_W2  = (const float*)d_in[18];
    const float* att_b2  = (const float*)d_in[19];
    const float* out_W   = (const float*)d_in[20];
    const float* out_b   = (const float*)d_in[21];
    float* out = (float*)d_out;

    float *s1, *core, *ctx, *att, *eff;
    cudaGetSymbolAddress((void**)&s1,   g_s1);
    cudaGetSymbolAddress((void**)&core, g_core);
    cudaGetSymbolAddress((void**)&ctx,  g_ctx);
    cudaGetSymbolAddress((void**)&att,  g_att);
    cudaGetSymbolAddress((void**)&eff,  g_eff);

    // 1. enc: s1 = LN(relu(state @ enc_W + b))
    gemm_fused<64, 256, 16, 8, 8, 0, 1><<<BKTOT / 64, 256>>>(
        state, nullptr, nullptr, enc_W, enc_b, enc_g, enc_bt, nullptr, nullptr,
        s1, BKTOT, HH, HH);

    // 2. core: gathered concat @ core_W, relu+LN
    gemm_fused<64, 256, 16, 8, 8, 1, 1><<<RR / 64, 256>>>(
        s1, nullptr, nullptr, core_W, core_b, core_g, core_bt, nullptr, nullptr,
        core, RR, 2 * HH, HH);

    // 3. ctx: core @ ctx_W, relu+LN
    gemm_fused<64, 256, 16, 8, 8, 0, 1><<<RR / 64, 256>>>(
        core, nullptr, nullptr, ctx_W, ctx_b, ctx_g, ctx_bt, nullptr, nullptr,
        ctx, RR, HH, HH);

    // 4. att: core @ att_W1, tanh+LN, @ att_W2, sigmoid -> scalar per row
    gemm_fused<64, 128, 16, 8, 4, 0, 2><<<RR / 64, 256>>>(
        core, nullptr, nullptr, att_W1, att_b1, att_g, att_bt, att_W2, att_b2,
        att, RR, HH, HAH);

    // 5. attention-weighted reduction over 7 partners
    effect_kernel<<<BKTOT, 256>>>(ctx, att, eff);

    // 6. out: [s1 | eff | x] @ out_W + b
    gemm_fused<64, 256, 16, 8, 8, 2, 0><<<BKTOT / 64, 256>>>(
        s1, eff, x, out_W, out_b, nullptr, nullptr, nullptr, nullptr,
        out, BKTOT, KOUT, HH);
}

// round 2
// speedup vs baseline: 2.0775x; 2.0775x over previous
#include <cuda_runtime.h>
#include <math.h>

typedef unsigned long long ull;

static constexpr int KK    = 8;
static constexpr int BKTOT = 16384;          // B*K rows
static constexpr int RR    = 114688;         // BKTOT*(K-1)
static constexpr int HH    = 250;
static constexpr int MX    = 576;
static constexpr int HP    = 256;            // padded hidden
static constexpr int BKt   = 16;

// ---------------- scratch (device globals; allocation-free) ----------------
__device__ __align__(16) float g_statep[BKTOT * HP];
__device__ __align__(16) float g_s1    [BKTOT * HP];
__device__ __align__(16) float g_core  [RR * HP];
__device__ __align__(16) float g_ctx   [RR * HP];
__device__ __align__(16) float g_att   [RR];
__device__ __align__(16) float g_eff   [BKTOT * HP];
__device__ __align__(16) float g_encW  [256 * 256];
__device__ __align__(16) float g_coreW [512 * 256];
__device__ __align__(16) float g_ctxW  [256 * 256];
__device__ __align__(16) float g_attW1 [256 * 128];
__device__ __align__(16) float g_outW  [1088 * 256];
__device__ __align__(16) float g_W2p   [128];

// ---------------- packed f32x2 helpers ----------------
__device__ __forceinline__ ull pack2(float v) {
    ull r; asm("mov.b64 %0, {%1, %1};" : "=l"(r) : "f"(v)); return r;
}
__device__ __forceinline__ void fma2(ull& acc, ull a, ull b) {
    asm("fma.rn.f32x2 %0, %1, %2, %0;" : "+l"(acc) : "l"(a), "l"(b));
}
__device__ __forceinline__ float2 unpack2(ull v) {
    float2 f; asm("mov.b64 {%0, %1}, %2;" : "=f"(f.x), "=f"(f.y) : "l"(v)); return f;
}

// ---------------- pad/copy prep ----------------
__global__ void pad_copy(float* __restrict__ dst, int dstride, int drow0, int ndrows,
                         const float* __restrict__ src, int scols, int srow0, int nsrows)
{
    int idx = blockIdx.x * blockDim.x + threadIdx.x;
    int total = ndrows * dstride;
    if (idx >= total) return;
    int r = idx / dstride, c = idx - r * dstride;
    float v = (r < nsrows && c < scols) ? src[(size_t)(srow0 + r) * scols + c] : 0.f;
    dst[(size_t)(drow0 + r) * dstride + c] = v;
}

// ---------------- fused GEMM ----------------
// GATHER: 0 plain A (stride astride); 1 pairwise concat gather from s1 (K'=512);
//         2 [s1 | eff | x] gather (K'=1088)
// EPI: 0 bias only (store stride cstride=N real, scalar); 1 relu+LN (padded float4 store);
//      2 tanh+LN+dot(W2)+sigmoid -> scalar per row
template<int BM, int BN, int GATHER, int EPI>
__global__ void __launch_bounds__(256, 2) gemm2(
    const float* __restrict__ A, const float* __restrict__ A2, const float* __restrict__ A3,
    const float* __restrict__ W, const float* __restrict__ bias,
    const float* __restrict__ gamma, const float* __restrict__ beta,
    const float* __restrict__ W2v, const float* __restrict__ b2,
    float* __restrict__ C, int Kp, int N, int astride, int cstride)
{
    constexpr int TM = 8, TN = 8;
    constexpr int TX = BN / TN, TY = BM / TM;
    static_assert(TX * TY == 256, "thread map");
    constexpr int AV = BM * BKt / 4 / 256;
    constexpr int BV = BKt * BN / 4 / 256;

    __shared__ __align__(16) float As[2][BKt][BM + 4];
    __shared__ __align__(16) float Bs[2][BKt][BN];

    const int tid  = threadIdx.x;
    const int tx   = tid % TX;
    const int ty   = tid / TX;
    const int row0 = blockIdx.x * BM;

    float4 ra[AV];
    float4 rb[BV];

    auto ldA = [&](int kt) {
#pragma unroll
        for (int v = 0; v < AV; v++) {
            int vid = tid + v * 256;
            int r   = vid >> 2;
            int gk  = kt + ((vid & 3) << 2);
            int gr  = row0 + r;
            const float* p;
            if (GATHER == 0) {
                p = A + (size_t)gr * astride + gk;
            } else if (GATHER == 1) {
                int b = gr / 56, rem = gr - b * 56;
                int i = rem / 7, jj = rem - i * 7;
                int j = jj + (jj >= i ? 1 : 0);
                p = (gk < HP) ? A + ((size_t)(b * KK + i) * HP + gk)
                              : A + ((size_t)(b * KK + j) * HP + gk - HP);
            } else {
                if (gk < HP)          p = A  + (size_t)gr * HP + gk;
                else if (gk < 2 * HP) p = A2 + (size_t)gr * HP + (gk - HP);
                else                  p = A3 + (size_t)gr * MX + (gk - 2 * HP);
            }
            ra[v] = *(const float4*)p;
        }
    };
    auto ldB = [&](int kt) {
#pragma unroll
        for (int v = 0; v < BV; v++) {
            int vid = tid + v * 256;
            int k   = vid / (BN / 4);
            int c   = (vid % (BN / 4)) << 2;
            rb[v] = *(const float4*)&W[(size_t)(kt + k) * BN + c];
        }
    };
    auto stA = [&](int buf) {
#pragma unroll
        for (int v = 0; v < AV; v++) {
            int vid = tid + v * 256;
            int r   = vid >> 2;
            int kq  = (vid & 3) << 2;
            As[buf][kq + 0][r] = ra[v].x;
            As[buf][kq + 1][r] = ra[v].y;
            As[buf][kq + 2][r] = ra[v].z;
            As[buf][kq + 3][r] = ra[v].w;
        }
    };
    auto stB = [&](int buf) {
#pragma unroll
        for (int v = 0; v < BV; v++) {
            int vid = tid + v * 256;
            int k   = vid / (BN / 4);
            int c   = (vid % (BN / 4)) << 2;
            *(float4*)&Bs[buf][k][c] = rb[v];
        }
    };

    ull acc[TM][TN / 2];
#pragma unroll
    for (int m = 0; m < TM; m++)
#pragma unroll
        for (int p = 0; p < TN / 2; p++) acc[m][p] = 0ull;

    ldA(0); ldB(0);
    stA(0); stB(0);
    __syncthreads();

    const int nk = Kp / BKt;
    for (int t = 0; t < nk; t++) {
        int cur = t & 1;
        if (t + 1 < nk) { ldA((t + 1) * BKt); ldB((t + 1) * BKt); }
#pragma unroll
        for (int k = 0; k < BKt; k++) {
            const float4 a0 = *(const float4*)&As[cur][k][ty * TM];
            const float4 a1 = *(const float4*)&As[cur][k][ty * TM + 4];
            const ull* bp = (const ull*)&Bs[cur][k][tx * TN];
            ull b0 = bp[0], b1 = bp[1], b2v = bp[2], b3 = bp[3];
            ull am[8];
            am[0] = pack2(a0.x); am[1] = pack2(a0.y); am[2] = pack2(a0.z); am[3] = pack2(a0.w);
            am[4] = pack2(a1.x); am[5] = pack2(a1.y); am[6] = pack2(a1.z); am[7] = pack2(a1.w);
#pragma unroll
            for (int m = 0; m < TM; m++) {
                fma2(acc[m][0], am[m], b0);
                fma2(acc[m][1], am[m], b1);
                fma2(acc[m][2], am[m], b2v);
                fma2(acc[m][3], am[m], b3);
            }
        }
        if (t + 1 < nk) { stA(cur ^ 1); stB(cur ^ 1); }
        __syncthreads();
    }

    // ---------------- epilogue ----------------
    float cv[TM][TN];
#pragma unroll
    for (int m = 0; m < TM; m++)
#pragma unroll
        for (int p = 0; p < TN / 2; p++) {
            float2 f = unpack2(acc[m][p]);
            cv[m][2 * p] = f.x; cv[m][2 * p + 1] = f.y;
        }

    float bia[TN];
#pragma unroll
    for (int n = 0; n < TN; n++) {
        int c = tx * TN + n;
        bia[n] = (c < N) ? bias[c] : 0.f;
    }

#pragma unroll
    for (int m = 0; m < TM; m++)
#pragma unroll
        for (int n = 0; n < TN; n++) {
            int c = tx * TN + n;
            float v = 0.f;
            if (c < N) {
                v = cv[m][n] + bia[n];
                if (EPI == 1) v = fmaxf(v, 0.f);
                if (EPI == 2) v = tanhf(v);
            }
            cv[m][n] = v;
        }

    if (EPI == 0) {
#pragma unroll
        for (int m = 0; m < TM; m++) {
            int gr = row0 + ty * TM + m;
#pragma unroll
            for (int n = 0; n < TN; n++) {
                int c = tx * TN + n;
                if (c < N) C[(size_t)gr * cstride + c] = cv[m][n];
            }
        }
        return;
    }

    // LayerNorm stats: per-row sums across the TX lanes owning the row
    float s[TM], q[TM];
#pragma unroll
    for (int m = 0; m < TM; m++) {
        float ss = 0.f, qq = 0.f;
#pragma unroll
        for (int n = 0; n < TN; n++) { float v = cv[m][n]; ss += v; qq += v * v; }
        s[m] = ss; q[m] = qq;
    }
#pragma unroll
    for (int off = TX / 2; off > 0; off >>= 1)
#pragma unroll
        for (int m = 0; m < TM; m++) {
            s[m] += __shfl_xor_sync(0xffffffffu, s[m], off);
            q[m] += __shfl_xor_sync(0xffffffffu, q[m], off);
        }

    float mu[TM], rs[TM];
    const float invN = 1.f / (float)N;
#pragma unroll
    for (int m = 0; m < TM; m++) {
        mu[m] = s[m] * invN;
        float var = q[m] * invN - mu[m] * mu[m];
        rs[m] = rsqrtf(var + 1e-5f);
    }

    if (EPI == 1) {
        float gv[TN], bv[TN];
#pragma unroll
        for (int n = 0; n < TN; n++) {
            int c = tx * TN + n;
            gv[n] = (c < N) ? gamma[c] : 0.f;
            bv[n] = (c < N) ? beta[c]  : 0.f;
        }
#pragma unroll
        for (int m = 0; m < TM; m++) {
            int gr = row0 + ty * TM + m;
            float w[TN];
#pragma unroll
            for (int n = 0; n < TN; n++) {
                int c = tx * TN + n;
                w[n] = (c < N) ? (cv[m][n] - mu[m]) * rs[m] * gv[n] + bv[n] : 0.f;
            }
            float4* dst = (float4*)&C[(size_t)gr * cstride + tx * TN];
            dst[0] = make_float4(w[0], w[1], w[2], w[3]);
            dst[1] = make_float4(w[4], w[5], w[6], w[7]);
        }
    } else { // EPI == 2
        float gv[TN], bv[TN], w2[TN];
#pragma unroll
        for (int n = 0; n < TN; n++) {
            int c = tx * TN + n;
            gv[n] = (c < N) ? gamma[c] : 0.f;
            bv[n] = (c < N) ? beta[c]  : 0.f;
            w2[n] = (c < N) ? W2v[c]   : 0.f;
        }
        float d[TM];
#pragma unroll
        for (int m = 0; m < TM; m++) {
            float dd = 0.f;
#pragma unroll
            for (int n = 0; n < TN; n++) {
                int c = tx * TN + n;
                if (c < N) {
                    float w = (cv[m][n] - mu[m]) * rs[m] * gv[n] + bv[n];
                    dd = fmaf(w, w2[n], dd);
                }
            }
            d[m] = dd;
        }
#pragma unroll
        for (int off = TX / 2; off > 0; off >>= 1)
#pragma unroll
            for (int m = 0; m < TM; m++)
                d[m] += __shfl_xor_sync(0xffffffffu, d[m], off);
        if (tx == 0) {
            float bb = b2[0];
#pragma unroll
            for (int m = 0; m < TM; m++) {
                int gr = row0 + ty * TM + m;
                C[gr] = 1.f / (1.f + expf(-(d[m] + bb)));
            }
        }
    }
}

// effect[bk, c] = sum_{jj<7} ctx[(bk*7+jj)*256 + c] * att[bk*7+jj], pads -> 0
__global__ void effect2(const float* __restrict__ ctx,
                        const float* __restrict__ att,
                        float* __restrict__ eff)
{
    int bk = blockIdx.x;
    __shared__ float a[7];
    if (threadIdx.x < 7) a[threadIdx.x] = att[bk * 7 + threadIdx.x];
    __syncthreads();
    int c = threadIdx.x;  // blockDim 256, one pass
    float s = 0.f;
    if (c < HH) {
        const float* p = ctx + (size_t)bk * 7 * HP + c;
#pragma unroll
        for (int jj = 0; jj < 7; jj++) s = fmaf(p[jj * HP], a[jj], s);
    }
    eff[(size_t)bk * HP + c] = s;
}

extern "C" void kernel_launch(void* const* d_in, const int* in_sizes, int n_in,
                              void* d_out, int out_size)
{
    const float* x       = (const float*)d_in[0];
    const float* state   = (const float*)d_in[1];
    const float* enc_W   = (const float*)d_in[2];
    const float* enc_b   = (const float*)d_in[3];
    const float* enc_g   = (const float*)d_in[4];
    const float* enc_bt  = (const float*)d_in[5];
    const float* core_W  = (const float*)d_in[6];
    const float* core_b  = (const float*)d_in[7];
    const float* core_g  = (const float*)d_in[8];
    const float* core_bt = (const float*)d_in[9];
    const float* ctx_W   = (const float*)d_in[10];
    const float* ctx_b   = (const float*)d_in[11];
    const float* ctx_g   = (const float*)d_in[12];
    const float* ctx_bt  = (const float*)d_in[13];
    const float* att_W1  = (const float*)d_in[14];
    const float* att_b1  = (const float*)d_in[15];
    const float* att_g   = (const float*)d_in[16];
    const float* att_bt  = (const float*)d_in[17];
    const float* att_W2  = (const float*)d_in[18];
    const float* att_b2  = (const float*)d_in[19];
    const float* out_W   = (const float*)d_in[20];
    const float* out_b   = (const float*)d_in[21];
    float* out = (float*)d_out;

    float *statep, *s1, *core, *ctx, *att, *eff;
    float *encW, *coreW, *ctxW, *attW1, *outW, *w2p;
    cudaGetSymbolAddress((void**)&statep, g_statep);
    cudaGetSymbolAddress((void**)&s1,     g_s1);
    cudaGetSymbolAddress((void**)&core,   g_core);
    cudaGetSymbolAddress((void**)&ctx,    g_ctx);
    cudaGetSymbolAddress((void**)&att,    g_att);
    cudaGetSymbolAddress((void**)&eff,    g_eff);
    cudaGetSymbolAddress((void**)&encW,   g_encW);
    cudaGetSymbolAddress((void**)&coreW,  g_coreW);
    cudaGetSymbolAddress((void**)&ctxW,   g_ctxW);
    cudaGetSymbolAddress((void**)&attW1,  g_attW1);
    cudaGetSymbolAddress((void**)&outW,   g_outW);
    cudaGetSymbolAddress((void**)&w2p,    g_W2p);

    auto PAD = [](float* dst, int dstride, int drow0, int ndrows,
                  const float* src, int scols, int srow0, int nsrows) {
        int tot = ndrows * dstride;
        pad_copy<<<(tot + 255) / 256, 256>>>(dst, dstride, drow0, ndrows,
                                             src, scols, srow0, nsrows);
    };
    // padded copies (zeros in all pad lanes)
    PAD(statep, 256, 0,   16384, state,  250, 0,   16384);
    PAD(encW,   256, 0,   256,   enc_W,  250, 0,   250);
    PAD(coreW,  256, 0,   256,   core_W, 250, 0,   250);
    PAD(coreW,  256, 256, 256,   core_W, 250, 250, 250);
    PAD(ctxW,   256, 0,   256,   ctx_W,  250, 0,   250);
    PAD(attW1,  128, 0,   256,   att_W1, 100, 0,   250);
    PAD(outW,   256, 0,   256,   out_W,  250, 0,   250);
    PAD(outW,   256, 256, 256,   out_W,  250, 250, 250);
    PAD(outW,   256, 512, 576,   out_W,  250, 500, 576);
    PAD(w2p,    128, 0,   1,     att_W2, 100, 0,   1);

    // 1. enc: s1 = LN(relu(state @ enc_W + b))
    gemm2<64, 256, 0, 1><<<BKTOT / 64, 256>>>(
        statep, nullptr, nullptr, encW, enc_b, enc_g, enc_bt, nullptr, nullptr,
        s1, 256, HH, 256, 256);

    // 2. core: gathered concat @ core_W, relu+LN
    gemm2<64, 256, 1, 1><<<RR / 64, 256>>>(
        s1, nullptr, nullptr, coreW, core_b, core_g, core_bt, nullptr, nullptr,
        core, 512, HH, 0, 256);

    // 3. ctx: core @ ctx_W, relu+LN
    gemm2<64, 256, 0, 1><<<RR / 64, 256>>>(
        core, nullptr, nullptr, ctxW, ctx_b, ctx_g, ctx_bt, nullptr, nullptr,
        ctx, 256, HH, 256, 256);

    // 4. att: core @ att_W1, tanh+LN, dot W2, sigmoid -> scalar per row
    gemm2<128, 128, 0, 2><<<RR / 128, 256>>>(
        core, nullptr, nullptr, attW1, att_b1, att_g, att_bt, w2p, att_b2,
        att, 256, 100, 256, 0);

    // 5. attention-weighted reduction over the 7 partners
    effect2<<<BKTOT, 256>>>(ctx, att, eff);

    // 6. out: [s1 | eff | x] @ out_W + b   (true-stride output)
    gemm2<64, 256, 2, 0><<<BKTOT / 64, 256>>>(
        s1, eff, x, outW, out_b, nullptr, nullptr, nullptr, nullptr,
        out, 1088, HH, 0, 250);
}

// round 4
// speedup vs baseline: 3.6604x; 1.7619x over previous
#include <cuda_runtime.h>
#include <cuda_bf16.h>
#include <math.h>
#include <stdint.h>

static constexpr int BKTOT = 16384;
static constexpr int RR    = 114688;

// ---------------- device-global scratch (allocation-free) ----------------
__device__ __align__(16) __nv_bfloat16 g_sp_h[16384*256], g_sp_l[16384*256];
__device__ __align__(16) __nv_bfloat16 g_xp_h[16384*576], g_xp_l[16384*576];
__device__ __align__(16) __nv_bfloat16 g_s1_h[16384*256], g_s1_l[16384*256];
__device__ __align__(16) __nv_bfloat16 g_co_h[114688*256], g_co_l[114688*256];
__device__ __align__(16) __nv_bfloat16 g_cx_h[114688*256], g_cx_l[114688*256];
__device__ __align__(16) float         g_att [114688];
__device__ __align__(16) __nv_bfloat16 g_ef_h[16384*256], g_ef_l[16384*256];
__device__ __align__(16) __nv_bfloat16 g_eW[256*768];
__device__ __align__(16) __nv_bfloat16 g_cW[256*1536];
__device__ __align__(16) __nv_bfloat16 g_xW[256*768];
__device__ __align__(16) __nv_bfloat16 g_aW[128*768];
__device__ __align__(16) __nv_bfloat16 g_oW[256*3264];

// ---------------- helpers ----------------
__device__ __forceinline__ uint32_t smem_u32(const void* p) {
    uint32_t a;
    asm("{ .reg .u64 t; cvta.to.shared.u64 t, %1; cvt.u32.u64 %0, t; }" : "=r"(a) : "l"(p));
    return a;
}
__device__ __forceinline__ void cpa16(uint32_t saddr, const void* g) {
    asm volatile("cp.async.cg.shared.global [%0], [%1], 16;" :: "r"(saddr), "l"(g));
}
#define CP_COMMIT() asm volatile("cp.async.commit_group;" ::: "memory")
#define CP_WAIT(n)  asm volatile("cp.async.wait_group %0;" :: "n"(n) : "memory")

__device__ __forceinline__ void mma_bf16(float* d, const uint32_t* a, const uint32_t* b) {
    asm volatile(
        "mma.sync.aligned.m16n8k16.row.col.f32.bf16.bf16.f32 "
        "{%0,%1,%2,%3}, {%4,%5,%6,%7}, {%8,%9}, {%0,%1,%2,%3};"
        : "+f"(d[0]), "+f"(d[1]), "+f"(d[2]), "+f"(d[3])
        : "r"(a[0]), "r"(a[1]), "r"(a[2]), "r"(a[3]), "r"(b[0]), "r"(b[1]));
}

// ---------------- prep kernels ----------------
__global__ void cvt_pad(__nv_bfloat16* __restrict__ dh, __nv_bfloat16* __restrict__ dl,
                        int DS, const float* __restrict__ src, int SC, int rows)
{
    int idx = blockIdx.x * blockDim.x + threadIdx.x;
    if (idx >= rows * DS) return;
    int r = idx / DS, c = idx - r * DS;
    float v = (c < SC) ? src[(size_t)r * SC + c] : 0.f;
    __nv_bfloat16 h = __float2bfloat16(v);
    dh[idx] = h;
    dl[idx] = __float2bfloat16(v - __bfloat162float(h));
}

// weight triple layout dst[n][KTRIP]: seg0 = hi, seg1 = lo, seg2 = hi (segments of KP)
// within a segment, up to 3 source pieces of widths 256/256/576 rows from W
__global__ void prep_w(__nv_bfloat16* __restrict__ dst, int KTRIP, int KP, int NP,
                       const float* __restrict__ W, int N0,
                       int b0, int v0, int b1, int v1, int b2, int v2)
{
    int idx = blockIdx.x * blockDim.x + threadIdx.x;
    if (idx >= NP * KTRIP) return;
    int n = idx / KTRIP, kk = idx - n * KTRIP;
    int seg = kk / KP, k = kk - seg * KP;
    bool lo = (seg == 1);
    int piece = (k >= 512) ? 2 : (k >= 256) ? 1 : 0;
    int off = k - ((piece == 2) ? 512 : piece * 256);
    int base  = (piece == 0) ? b0 : (piece == 1) ? b1 : b2;
    int valid = (piece == 0) ? v0 : (piece == 1) ? v1 : v2;
    float v = (n < N0 && off < valid) ? W[(size_t)(base + off) * N0 + n] : 0.f;
    __nv_bfloat16 h = __float2bfloat16(v);
    if (lo) h = __float2bfloat16(v - __bfloat162float(h));
    dst[idx] = h;
}

// ---------------- HMMA fused GEMM ----------------
// A-triple per row: [a_hi | a_hi | a_lo] assembled at load; Bw pre-baked [N][KTRIP]=[hi|lo|hi]
// GATHER: 0 plain (KP=256), 1 pairwise concat (KP=512), 2 [s1|eff|x] (KP=1088)
// EPI: 0 bias->fp32 (stride N); 1 relu+LN -> hi/lo planes (stride 256); 2 tanh+LN+dot W2+sigmoid
template<int BM, int BN, int KTRIP, int GATHER, int EPI>
__global__ void __launch_bounds__(256) hgemm(
    const __nv_bfloat16* __restrict__ A1h, const __nv_bfloat16* __restrict__ A1l,
    const __nv_bfloat16* __restrict__ A2h, const __nv_bfloat16* __restrict__ A2l,
    const __nv_bfloat16* __restrict__ A3h, const __nv_bfloat16* __restrict__ A3l,
    const __nv_bfloat16* __restrict__ Bw,
    const float* __restrict__ bias, const float* __restrict__ gamma, const float* __restrict__ beta,
    const float* __restrict__ W2, const float* __restrict__ b2,
    float* __restrict__ Cf, __nv_bfloat16* __restrict__ Chi, __nv_bfloat16* __restrict__ Clo,
    int N)
{
    constexpr int PADK = 72;            // halves; 36 words, 36%32==4 -> conflict-free frags
    constexpr int NWM = BM / 32, NWN = BN / 64;
    constexpr int NST = KTRIP / 64;
    static_assert(NWM * NWN == 8, "warp map");

    extern __shared__ __align__(16) __nv_bfloat16 sm[];
    __nv_bfloat16* const Asm = sm;
    __nv_bfloat16* const Bsm = sm + 2 * BM * PADK;
    float* const redS = (float*)(sm + 2 * (BM + BN) * PADK);
    float* const redQ = redS + BM * NWN;
    const uint32_t smb = smem_u32(sm);

    const int tid = threadIdx.x, w = tid >> 5, lane = tid & 31;
    const int g = lane >> 2, tq = lane & 3;
    const int wm = w % NWM, wn = w / NWM;
    const int row0 = blockIdx.x * BM;

    float acc[2][8][4];
#pragma unroll
    for (int mi = 0; mi < 2; mi++)
#pragma unroll
        for (int ni = 0; ni < 8; ni++)
#pragma unroll
            for (int e = 0; e < 4; e++) acc[mi][ni][e] = 0.f;

    auto gatherA = [&](int gr, int kk) -> const __nv_bfloat16* {
        if (GATHER == 0) {
            int seg = kk >> 8, k = kk & 255;
            return ((seg == 2) ? A1l : A1h) + (size_t)gr * 256 + k;
        } else if (GATHER == 1) {
            int seg = kk / 512, k = kk - seg * 512;
            const __nv_bfloat16* P = (seg == 2) ? A1l : A1h;
            int b = gr / 56, rem = gr - b * 56;
            int i = rem / 7, jj = rem - i * 7;
            int j = jj + (jj >= i ? 1 : 0);
            int sr = (k < 256) ? (b * 8 + i) : (b * 8 + j);
            return P + (size_t)sr * 256 + (k & 255);
        } else {
            int seg = kk / 1088, k = kk - seg * 1088;
            bool lo = (seg == 2);
            if (k < 256) return (lo ? A1l : A1h) + (size_t)gr * 256 + k;
            if (k < 512) return (lo ? A2l : A2h) + (size_t)gr * 256 + (k - 256);
            return (lo ? A3l : A3h) + (size_t)gr * 576 + (k - 512);
        }
    };

    auto loadStage = [&](int t, int st) {
        int kb = t * 64;
#pragma unroll
        for (int u = tid; u < BM * 8; u += 256) {
            int r = u >> 3, cq = u & 7;
            cpa16(smb + (((st * BM + r) * PADK + cq * 8) << 1), gatherA(row0 + r, kb + cq * 8));
        }
#pragma unroll
        for (int u = tid; u < BN * 8; u += 256) {
            int r = u >> 3, cq = u & 7;
            cpa16(smb + ((2 * BM * PADK + (st * BN + r) * PADK + cq * 8) << 1),
                  Bw + (size_t)r * KTRIP + kb + cq * 8);
        }
    };

    auto compute = [&](int st) {
        const __nv_bfloat16* At = Asm + st * BM * PADK;
        const __nv_bfloat16* Bt = Bsm + st * BN * PADK;
#pragma unroll
        for (int kk = 0; kk < 4; kk++) {
            uint32_t a[2][4], b[8][2];
            const int k = kk * 16 + tq * 2;
#pragma unroll
            for (int mi = 0; mi < 2; mi++) {
                int r = wm * 32 + mi * 16 + g;
                a[mi][0] = *(const uint32_t*)(At + r * PADK + k);
                a[mi][1] = *(const uint32_t*)(At + (r + 8) * PADK + k);
                a[mi][2] = *(const uint32_t*)(At + r * PADK + k + 8);
                a[mi][3] = *(const uint32_t*)(At + (r + 8) * PADK + k + 8);
            }
#pragma unroll
            for (int ni = 0; ni < 8; ni++) {
                int r = wn * 64 + ni * 8 + g;
                b[ni][0] = *(const uint32_t*)(Bt + r * PADK + k);
                b[ni][1] = *(const uint32_t*)(Bt + r * PADK + k + 8);
            }
#pragma unroll
            for (int mi = 0; mi < 2; mi++)
#pragma unroll
                for (int ni = 0; ni < 8; ni++)
                    mma_bf16(acc[mi][ni], a[mi], b[ni]);
        }
    };

    loadStage(0, 0);
    CP_COMMIT();
    for (int t = 0; t < NST; t++) {
        if (t + 1 < NST) {
            loadStage(t + 1, (t + 1) & 1);
            CP_COMMIT();
            CP_WAIT(1);
        } else {
            CP_WAIT(0);
        }
        __syncthreads();
        compute(t & 1);
        __syncthreads();
    }

    // ---------------- epilogue ----------------
    if (EPI == 0) {
#pragma unroll
        for (int mi = 0; mi < 2; mi++) {
            int r0 = row0 + wm * 32 + mi * 16 + g;
#pragma unroll
            for (int ni = 0; ni < 8; ni++) {
                int c0 = wn * 64 + ni * 8 + tq * 2, c1 = c0 + 1;
                if (c0 < N) {
                    Cf[(size_t)r0 * N + c0]       = acc[mi][ni][0] + bias[c0];
                    Cf[(size_t)(r0 + 8) * N + c0] = acc[mi][ni][2] + bias[c0];
                }
                if (c1 < N) {
                    Cf[(size_t)r0 * N + c1]       = acc[mi][ni][1] + bias[c1];
                    Cf[(size_t)(r0 + 8) * N + c1] = acc[mi][ni][3] + bias[c1];
                }
            }
        }
        return;
    }

    // bias + activation, zero pads, accumulate row stats
    float s[2][2] = {{0, 0}, {0, 0}}, q[2][2] = {{0, 0}, {0, 0}};
#pragma unroll
    for (int mi = 0; mi < 2; mi++)
#pragma unroll
        for (int ni = 0; ni < 8; ni++) {
            int c0 = wn * 64 + ni * 8 + tq * 2, c1 = c0 + 1;
            float b0v = (c0 < N) ? bias[c0] : 0.f;
            float b1v = (c1 < N) ? bias[c1] : 0.f;
            float v0 = acc[mi][ni][0] + b0v, v1 = acc[mi][ni][1] + b1v;
            float v2 = acc[mi][ni][2] + b0v, v3 = acc[mi][ni][3] + b1v;
            if (EPI == 1) {
                v0 = fmaxf(v0, 0.f); v1 = fmaxf(v1, 0.f);
                v2 = fmaxf(v2, 0.f); v3 = fmaxf(v3, 0.f);
            } else {
                v0 = tanhf(v0); v1 = tanhf(v1); v2 = tanhf(v2); v3 = tanhf(v3);
            }
            if (c0 >= N) { v0 = 0.f; v2 = 0.f; }
            if (c1 >= N) { v1 = 0.f; v3 = 0.f; }
            acc[mi][ni][0] = v0; acc[mi][ni][1] = v1;
            acc[mi][ni][2] = v2; acc[mi][ni][3] = v3;
            s[mi][0] += v0 + v1; q[mi][0] += v0 * v0 + v1 * v1;
            s[mi][1] += v2 + v3; q[mi][1] += v2 * v2 + v3 * v3;
        }
#pragma unroll
    for (int off = 1; off <= 2; off <<= 1)
#pragma unroll
        for (int mi = 0; mi < 2; mi++)
#pragma unroll
            for (int dr = 0; dr < 2; dr++) {
                s[mi][dr] += __shfl_xor_sync(0xffffffffu, s[mi][dr], off);
                q[mi][dr] += __shfl_xor_sync(0xffffffffu, q[mi][dr], off);
            }
    if (tq == 0) {
#pragma unroll
        for (int mi = 0; mi < 2; mi++)
#pragma unroll
            for (int dr = 0; dr < 2; dr++) {
                int r = wm * 32 + mi * 16 + g + 8 * dr;
                redS[r * NWN + wn] = s[mi][dr];
                redQ[r * NWN + wn] = q[mi][dr];
            }
    }
    __syncthreads();

    float mu[2][2], rs[2][2];
    const float invN = 1.f / (float)N;
#pragma unroll
    for (int mi = 0; mi < 2; mi++)
#pragma unroll
        for (int dr = 0; dr < 2; dr++) {
            int r = wm * 32 + mi * 16 + g + 8 * dr;
            float ss = 0.f, qq = 0.f;
#pragma unroll
            for (int x = 0; x < NWN; x++) { ss += redS[r * NWN + x]; qq += redQ[r * NWN + x]; }
            mu[mi][dr] = ss * invN;
            rs[mi][dr] = rsqrtf(qq * invN - mu[mi][dr] * mu[mi][dr] + 1e-5f);
        }

    if (EPI == 1) {
#pragma unroll
        for (int mi = 0; mi < 2; mi++) {
            int gr0 = row0 + wm * 32 + mi * 16 + g;
#pragma unroll
            for (int ni = 0; ni < 8; ni++) {
                int c0 = wn * 64 + ni * 8 + tq * 2, c1 = c0 + 1;
                float g0 = (c0 < N) ? gamma[c0] : 0.f, g1 = (c1 < N) ? gamma[c1] : 0.f;
                float t0 = (c0 < N) ? beta[c0] : 0.f,  t1 = (c1 < N) ? beta[c1] : 0.f;
#pragma unroll
                for (int dr = 0; dr < 2; dr++) {
                    int gr = gr0 + 8 * dr;
                    float w0 = (c0 < N) ? (acc[mi][ni][2 * dr + 0] - mu[mi][dr]) * rs[mi][dr] * g0 + t0 : 0.f;
                    float w1 = (c1 < N) ? (acc[mi][ni][2 * dr + 1] - mu[mi][dr]) * rs[mi][dr] * g1 + t1 : 0.f;
                    __nv_bfloat16 h0 = __float2bfloat16(w0), h1 = __float2bfloat16(w1);
                    __nv_bfloat16 l0 = __float2bfloat16(w0 - __bfloat162float(h0));
                    __nv_bfloat16 l1 = __float2bfloat16(w1 - __bfloat162float(h1));
                    *(__nv_bfloat162*)(Chi + (size_t)gr * 256 + c0) = __halves2bfloat162(h0, h1);
                    *(__nv_bfloat162*)(Clo + (size_t)gr * 256 + c0) = __halves2bfloat162(l0, l1);
                }
            }
        }
    } else { // EPI == 2
        float d[2][2] = {{0, 0}, {0, 0}};
#pragma unroll
        for (int mi = 0; mi < 2; mi++)
#pragma unroll
            for (int ni = 0; ni < 8; ni++) {
                int c0 = wn * 64 + ni * 8 + tq * 2, c1 = c0 + 1;
#pragma unroll
                for (int dr = 0; dr < 2; dr++) {
                    if (c0 < N)
                        d[mi][dr] += ((acc[mi][ni][2 * dr + 0] - mu[mi][dr]) * rs[mi][dr] * gamma[c0] + beta[c0]) * W2[c0];
                    if (c1 < N)
                        d[mi][dr] += ((acc[mi][ni][2 * dr + 1] - mu[mi][dr]) * rs[mi][dr] * gamma[c1] + beta[c1]) * W2[c1];
                }
            }
#pragma unroll
        for (int off = 1; off <= 2; off <<= 1)
#pragma unroll
            for (int mi = 0; mi < 2; mi++)
#pragma unroll
                for (int dr = 0; dr < 2; dr++)
                    d[mi][dr] += __shfl_xor_sync(0xffffffffu, d[mi][dr], off);
        __syncthreads();  // redS reuse
        if (tq == 0) {
#pragma unroll
            for (int mi = 0; mi < 2; mi++)
#pragma unroll
                for (int dr = 0; dr < 2; dr++) {
                    int r = wm * 32 + mi * 16 + g + 8 * dr;
                    redS[r * NWN + wn] = d[mi][dr];
                }
        }
        __syncthreads();
        if (wn == 0 && tq == 0) {
            float bb = b2[0];
#pragma unroll
            for (int mi = 0; mi < 2; mi++)
#pragma unroll
                for (int dr = 0; dr < 2; dr++) {
                    int r = wm * 32 + mi * 16 + g + 8 * dr;
                    float dd = 0.f;
#pragma unroll
                    for (int x = 0; x < NWN; x++) dd += redS[r * NWN + x];
                    Cf[row0 + r] = 1.f / (1.f + expf(-(dd + bb)));
                }
        }
    }
}

// effect: eff[bk][c] = sum_j (ctx_hi+ctx_lo)[bk*7+j][c] * att[bk*7+j], stored hi/lo
__global__ void effect3(const __nv_bfloat16* __restrict__ ch, const __nv_bfloat16* __restrict__ cl,
                        const float* __restrict__ att,
                        __nv_bfloat16* __restrict__ eh, __nv_bfloat16* __restrict__ el)
{
    int bk = blockIdx.x, c = threadIdx.x;
    __shared__ float a[7];
    if (c < 7) a[c] = att[bk * 7 + c];
    __syncthreads();
    size_t base = (size_t)bk * 7 * 256 + c;
    float s = 0.f;
#pragma unroll
    for (int j = 0; j < 7; j++)
        s = fmaf(__bfloat162float(ch[base + j * 256]) + __bfloat162float(cl[base + j * 256]),
                 a[j], s);
    __nv_bfloat16 h = __float2bfloat16(s);
    eh[(size_t)bk * 256 + c] = h;
    el[(size_t)bk * 256 + c] = __float2bfloat16(s - __bfloat162float(h));
}

extern "C" void kernel_launch(void* const* d_in, const int* in_sizes, int n_in,
                              void* d_out, int out_size)
{
    const float* x       = (const float*)d_in[0];
    const float* state   = (const float*)d_in[1];
    const float* enc_W   = (const float*)d_in[2];
    const float* enc_b   = (const float*)d_in[3];
    const float* enc_g   = (const float*)d_in[4];
    const float* enc_bt  = (const float*)d_in[5];
    const float* core_W  = (const float*)d_in[6];
    const float* core_b  = (const float*)d_in[7];
    const float* core_g  = (const float*)d_in[8];
    const float* core_bt = (const float*)d_in[9];
    const float* ctx_W   = (const float*)d_in[10];
    const float* ctx_b   = (const float*)d_in[11];
    const float* ctx_g   = (const float*)d_in[12];
    const float* ctx_bt  = (const float*)d_in[13];
    const float* att_W1  = (const float*)d_in[14];
    const float* att_b1  = (const float*)d_in[15];
    const float* att_g   = (const float*)d_in[16];
    const float* att_bt  = (const float*)d_in[17];
    const float* att_W2  = (const float*)d_in[18];
    const float* att_b2  = (const float*)d_in[19];
    const float* out_W   = (const float*)d_in[20];
    const float* out_b   = (const float*)d_in[21];
    float* out = (float*)d_out;

    __nv_bfloat16 *sp_h, *sp_l, *xp_h, *xp_l, *s1_h, *s1_l, *co_h, *co_l, *cx_h, *cx_l;
    __nv_bfloat16 *ef_h, *ef_l, *eW, *cW, *xW, *aW, *oW;
    float* att;
    cudaGetSymbolAddress((void**)&sp_h, g_sp_h); cudaGetSymbolAddress((void**)&sp_l, g_sp_l);
    cudaGetSymbolAddress((void**)&xp_h, g_xp_h); cudaGetSymbolAddress((void**)&xp_l, g_xp_l);
    cudaGetSymbolAddress((void**)&s1_h, g_s1_h); cudaGetSymbolAddress((void**)&s1_l, g_s1_l);
    cudaGetSymbolAddress((void**)&co_h, g_co_h); cudaGetSymbolAddress((void**)&co_l, g_co_l);
    cudaGetSymbolAddress((void**)&cx_h, g_cx_h); cudaGetSymbolAddress((void**)&cx_l, g_cx_l);
    cudaGetSymbolAddress((void**)&ef_h, g_ef_h); cudaGetSymbolAddress((void**)&ef_l, g_ef_l);
    cudaGetSymbolAddress((void**)&eW, g_eW);     cudaGetSymbolAddress((void**)&cW, g_cW);
    cudaGetSymbolAddress((void**)&xW, g_xW);     cudaGetSymbolAddress((void**)&aW, g_aW);
    cudaGetSymbolAddress((void**)&oW, g_oW);     cudaGetSymbolAddress((void**)&att, g_att);

    const int SM_STD = 2 * (64 + 256) * 72 * 2 + 64 * 4 * 2 * 4;    // 94208
    const int SM_ATT = 2 * (128 + 128) * 72 * 2 + 128 * 2 * 2 * 4;  // 75776
    cudaFuncSetAttribute((const void*)hgemm<64, 256, 768, 0, 1>,  cudaFuncAttributeMaxDynamicSharedMemorySize, SM_STD);
    cudaFuncSetAttribute((const void*)hgemm<64, 256, 1536, 1, 1>, cudaFuncAttributeMaxDynamicSharedMemorySize, SM_STD);
    cudaFuncSetAttribute((const void*)hgemm<128, 128, 768, 0, 2>, cudaFuncAttributeMaxDynamicSharedMemorySize, SM_ATT);
    cudaFuncSetAttribute((const void*)hgemm<64, 256, 3264, 2, 0>, cudaFuncAttributeMaxDynamicSharedMemorySize, SM_STD);

    // prep
    cvt_pad<<<(16384 * 256) / 256, 256>>>(sp_h, sp_l, 256, state, 250, 16384);
    cvt_pad<<<(16384 * 576) / 256, 256>>>(xp_h, xp_l, 576, x, 576, 16384);
    prep_w<<<(256 * 768) / 256, 256>>>(eW, 768, 256, 256, enc_W, 250, 0, 250, 0, 0, 0, 0);
    prep_w<<<(256 * 1536) / 256, 256>>>(cW, 1536, 512, 256, core_W, 250, 0, 250, 250, 250, 0, 0);
    prep_w<<<(256 * 768) / 256, 256>>>(xW, 768, 256, 256, ctx_W, 250, 0, 250, 0, 0, 0, 0);
    prep_w<<<(128 * 768) / 256, 256>>>(aW, 768, 256, 128, att_W1, 100, 0, 250, 0, 0, 0, 0);
    prep_w<<<(256 * 3264) / 256, 256>>>(oW, 3264, 1088, 256, out_W, 250, 0, 250, 250, 250, 500, 576);

    // 1. enc
    hgemm<64, 256, 768, 0, 1><<<BKTOT / 64, 256, SM_STD>>>(
        sp_h, sp_l, nullptr, nullptr, nullptr, nullptr, eW,
        enc_b, enc_g, enc_bt, nullptr, nullptr,
        nullptr, s1_h, s1_l, 250);
    // 2. core (pairwise concat gather)
    hgemm<64, 256, 1536, 1, 1><<<RR / 64, 256, SM_STD>>>(
        s1_h, s1_l, nullptr, nullptr, nullptr, nullptr, cW,
        core_b, core_g, core_bt, nullptr, nullptr,
        nullptr, co_h, co_l, 250);
    // 3. ctx
    hgemm<64, 256, 768, 0, 1><<<RR / 64, 256, SM_STD>>>(
        co_h, co_l, nullptr, nullptr, nullptr, nullptr, xW,
        ctx_b, ctx_g, ctx_bt, nullptr, nullptr,
        nullptr, cx_h, cx_l, 250);
    // 4. att scores
    hgemm<128, 128, 768, 0, 2><<<RR / 128, 256, SM_ATT>>>(
        co_h, co_l, nullptr, nullptr, nullptr, nullptr, aW,
        att_b1, att_g, att_bt, att_W2, att_b2,
        att, nullptr, nullptr, 100);
    // 5. attention-weighted reduction
    effect3<<<BKTOT, 256>>>(cx_h, cx_l, att, ef_h, ef_l);
    // 6. out
    hgemm<64, 256, 3264, 2, 0><<<BKTOT / 64, 256, SM_STD>>>(
        s1_h, s1_l, ef_h, ef_l, xp_h, xp_l, oW,
        out_b, nullptr, nullptr, nullptr, nullptr,
        out, nullptr, nullptr, 250);
}

// round 5
// speedup vs baseline: 4.5608x; 1.2460x over previous
#include <cuda_runtime.h>
#include <cuda_bf16.h>
#include <math.h>
#include <stdint.h>

static constexpr int BKTOT = 16384;
static constexpr int RR    = 114688;

// ---------------- device-global scratch (allocation-free) ----------------
__device__ __align__(16) __nv_bfloat16 g_sp_h[16384*256], g_sp_l[16384*256];
__device__ __align__(16) __nv_bfloat16 g_xp_h[16384*576], g_xp_l[16384*576];
__device__ __align__(16) __nv_bfloat16 g_s1_h[16384*256], g_s1_l[16384*256];
__device__ __align__(16) float         g_uv  [16384*512];
__device__ __align__(16) __nv_bfloat16 g_co_h[114688*256], g_co_l[114688*256];
__device__ __align__(16) __nv_bfloat16 g_cx_h[114688*256], g_cx_l[114688*256];
__device__ __align__(16) float         g_att [114688];
__device__ __align__(16) __nv_bfloat16 g_ef_h[16384*256], g_ef_l[16384*256];
__device__ __align__(16) __nv_bfloat16 g_eW[256*768];
__device__ __align__(16) __nv_bfloat16 g_uvW[512*768];
__device__ __align__(16) __nv_bfloat16 g_xW[256*768];
__device__ __align__(16) __nv_bfloat16 g_aW[128*768];
__device__ __align__(16) __nv_bfloat16 g_oW[256*3264];

// ---------------- helpers ----------------
__device__ __forceinline__ uint32_t smem_u32(const void* p) {
    uint32_t a;
    asm("{ .reg .u64 t; cvta.to.shared.u64 t, %1; cvt.u32.u64 %0, t; }" : "=r"(a) : "l"(p));
    return a;
}
__device__ __forceinline__ void cpa16(uint32_t saddr, const void* g) {
    asm volatile("cp.async.cg.shared.global [%0], [%1], 16;" :: "r"(saddr), "l"(g));
}
#define CP_COMMIT() asm volatile("cp.async.commit_group;" ::: "memory")
#define CP_WAIT(n)  asm volatile("cp.async.wait_group %0;" :: "n"(n) : "memory")

__device__ __forceinline__ void mma_bf16(float* d, const uint32_t* a, const uint32_t* b) {
    asm volatile(
        "mma.sync.aligned.m16n8k16.row.col.f32.bf16.bf16.f32 "
        "{%0,%1,%2,%3}, {%4,%5,%6,%7}, {%8,%9}, {%0,%1,%2,%3};"
        : "+f"(d[0]), "+f"(d[1]), "+f"(d[2]), "+f"(d[3])
        : "r"(a[0]), "r"(a[1]), "r"(a[2]), "r"(a[3]), "r"(b[0]), "r"(b[1]));
}

// ---------------- prep kernels ----------------
__global__ void cvt_pad(__nv_bfloat16* __restrict__ dh, __nv_bfloat16* __restrict__ dl,
                        int DS, const float* __restrict__ src, int SC, int rows)
{
    int idx = blockIdx.x * blockDim.x + threadIdx.x;
    if (idx >= rows * DS) return;
    int r = idx / DS, c = idx - r * DS;
    float v = (c < SC) ? src[(size_t)r * SC + c] : 0.f;
    __nv_bfloat16 h = __float2bfloat16(v);
    dh[idx] = h;
    dl[idx] = __float2bfloat16(v - __bfloat162float(h));
}

// weight triple layout dst[n][KTRIP]: seg0 = hi, seg1 = lo, seg2 = hi (segments of KP)
__global__ void prep_w(__nv_bfloat16* __restrict__ dst, int KTRIP, int KP, int NP,
                       const float* __restrict__ W, int N0,
                       int b0, int v0, int b1, int v1, int b2, int v2)
{
    int idx = blockIdx.x * blockDim.x + threadIdx.x;
    if (idx >= NP * KTRIP) return;
    int n = idx / KTRIP, kk = idx - n * KTRIP;
    int seg = kk / KP, k = kk - seg * KP;
    bool lo = (seg == 1);
    int piece = (k >= 512) ? 2 : (k >= 256) ? 1 : 0;
    int off = k - ((piece == 2) ? 512 : piece * 256);
    int base  = (piece == 0) ? b0 : (piece == 1) ? b1 : b2;
    int valid = (piece == 0) ? v0 : (piece == 1) ? v1 : v2;
    float v = (n < N0 && off < valid) ? W[(size_t)(base + off) * N0 + n] : 0.f;
    __nv_bfloat16 h = __float2bfloat16(v);
    if (lo) h = __float2bfloat16(v - __bfloat162float(h));
    dst[idx] = h;
}

// ---------------- HMMA fused GEMM ----------------
// A-triple per row: [a_hi | a_hi | a_lo] assembled at load; Bw pre-baked [N][KTRIP]=[hi|lo|hi]
// GATHER: 0 plain (KP=256), 2 [s1|eff|x] (KP=1088)
// EPI: 0 bias?+store fp32 (cstride); 1 relu+LN -> hi/lo planes (stride 256); 2 tanh+LN+dot W2+sigmoid
template<int BM, int BN, int KTRIP, int GATHER, int EPI>
__global__ void __launch_bounds__(256) hgemm(
    const __nv_bfloat16* __restrict__ A1h, const __nv_bfloat16* __restrict__ A1l,
    const __nv_bfloat16* __restrict__ A2h, const __nv_bfloat16* __restrict__ A2l,
    const __nv_bfloat16* __restrict__ A3h, const __nv_bfloat16* __restrict__ A3l,
    const __nv_bfloat16* __restrict__ Bw,
    const float* __restrict__ bias, const float* __restrict__ gamma, const float* __restrict__ beta,
    const float* __restrict__ W2, const float* __restrict__ b2,
    float* __restrict__ Cf, __nv_bfloat16* __restrict__ Chi, __nv_bfloat16* __restrict__ Clo,
    int N, int cstride)
{
    constexpr int PADK = 72;            // halves; 36 words, 36%32==4 -> conflict-free frags
    constexpr int NWM = BM / 32, NWN = BN / 64;
    constexpr int NST = KTRIP / 64;
    static_assert(NWM * NWN == 8, "warp map");

    extern __shared__ __align__(16) __nv_bfloat16 sm[];
    __nv_bfloat16* const Asm = sm;
    __nv_bfloat16* const Bsm = sm + 2 * BM * PADK;
    float* const redS = (float*)(sm + 2 * (BM + BN) * PADK);
    float* const redQ = redS + BM * NWN;
    const uint32_t smb = smem_u32(sm);

    const int tid = threadIdx.x, w = tid >> 5, lane = tid & 31;
    const int g = lane >> 2, tq = lane & 3;
    const int wm = w % NWM, wn = w / NWM;
    const int row0 = blockIdx.x * BM;
    const int col0 = blockIdx.y * BN;
    Bw += (size_t)col0 * KTRIP;

    float acc[2][8][4];
#pragma unroll
    for (int mi = 0; mi < 2; mi++)
#pragma unroll
        for (int ni = 0; ni < 8; ni++)
#pragma unroll
            for (int e = 0; e < 4; e++) acc[mi][ni][e] = 0.f;

    auto gatherA = [&](int gr, int kk) -> const __nv_bfloat16* {
        if (GATHER == 0) {
            int seg = kk >> 8, k = kk & 255;
            return ((seg == 2) ? A1l : A1h) + (size_t)gr * 256 + k;
        } else {
            int seg = kk / 1088, k = kk - seg * 1088;
            bool lo = (seg == 2);
            if (k < 256) return (lo ? A1l : A1h) + (size_t)gr * 256 + k;
            if (k < 512) return (lo ? A2l : A2h) + (size_t)gr * 256 + (k - 256);
            return (lo ? A3l : A3h) + (size_t)gr * 576 + (k - 512);
        }
    };

    auto loadStage = [&](int t, int st) {
        int kb = t * 64;
#pragma unroll
        for (int u = tid; u < BM * 8; u += 256) {
            int r = u >> 3, cq = u & 7;
            cpa16(smb + (((st * BM + r) * PADK + cq * 8) << 1), gatherA(row0 + r, kb + cq * 8));
        }
#pragma unroll
        for (int u = tid; u < BN * 8; u += 256) {
            int r = u >> 3, cq = u & 7;
            cpa16(smb + ((2 * BM * PADK + (st * BN + r) * PADK + cq * 8) << 1),
                  Bw + (size_t)r * KTRIP + kb + cq * 8);
        }
    };

    auto compute = [&](int st) {
        const __nv_bfloat16* At = Asm + st * BM * PADK;
        const __nv_bfloat16* Bt = Bsm + st * BN * PADK;
#pragma unroll
        for (int kk = 0; kk < 4; kk++) {
            uint32_t a[2][4], b[8][2];
            const int k = kk * 16 + tq * 2;
#pragma unroll
            for (int mi = 0; mi < 2; mi++) {
                int r = wm * 32 + mi * 16 + g;
                a[mi][0] = *(const uint32_t*)(At + r * PADK + k);
                a[mi][1] = *(const uint32_t*)(At + (r + 8) * PADK + k);
                a[mi][2] = *(const uint32_t*)(At + r * PADK + k + 8);
                a[mi][3] = *(const uint32_t*)(At + (r + 8) * PADK + k + 8);
            }
#pragma unroll
            for (int ni = 0; ni < 8; ni++) {
                int r = wn * 64 + ni * 8 + g;
                b[ni][0] = *(const uint32_t*)(Bt + r * PADK + k);
                b[ni][1] = *(const uint32_t*)(Bt + r * PADK + k + 8);
            }
#pragma unroll
            for (int mi = 0; mi < 2; mi++)
#pragma unroll
                for (int ni = 0; ni < 8; ni++)
                    mma_bf16(acc[mi][ni], a[mi], b[ni]);
        }
    };

    loadStage(0, 0);
    CP_COMMIT();
    for (int t = 0; t < NST; t++) {
        if (t + 1 < NST) {
            loadStage(t + 1, (t + 1) & 1);
            CP_COMMIT();
            CP_WAIT(1);
        } else {
            CP_WAIT(0);
        }
        __syncthreads();
        compute(t & 1);
        __syncthreads();
    }

    // ---------------- epilogue ----------------
    if (EPI == 0) {
#pragma unroll
        for (int mi = 0; mi < 2; mi++) {
            int r0 = row0 + wm * 32 + mi * 16 + g;
#pragma unroll
            for (int ni = 0; ni < 8; ni++) {
                int c0 = wn * 64 + ni * 8 + tq * 2, c1 = c0 + 1;
                if (c0 < N) {
                    float bv = bias ? bias[c0] : 0.f;
                    Cf[(size_t)r0 * cstride + col0 + c0]       = acc[mi][ni][0] + bv;
                    Cf[(size_t)(r0 + 8) * cstride + col0 + c0] = acc[mi][ni][2] + bv;
                }
                if (c1 < N) {
                    float bv = bias ? bias[c1] : 0.f;
                    Cf[(size_t)r0 * cstride + col0 + c1]       = acc[mi][ni][1] + bv;
                    Cf[(size_t)(r0 + 8) * cstride + col0 + c1] = acc[mi][ni][3] + bv;
                }
            }
        }
        return;
    }

    // bias + activation, zero pads, accumulate row stats
    float s[2][2] = {{0, 0}, {0, 0}}, q[2][2] = {{0, 0}, {0, 0}};
#pragma unroll
    for (int mi = 0; mi < 2; mi++)
#pragma unroll
        for (int ni = 0; ni < 8; ni++) {
            int c0 = wn * 64 + ni * 8 + tq * 2, c1 = c0 + 1;
            float b0v = (c0 < N) ? bias[c0] : 0.f;
            float b1v = (c1 < N) ? bias[c1] : 0.f;
            float v0 = acc[mi][ni][0] + b0v, v1 = acc[mi][ni][1] + b1v;
            float v2 = acc[mi][ni][2] + b0v, v3 = acc[mi][ni][3] + b1v;
            if (EPI == 1) {
                v0 = fmaxf(v0, 0.f); v1 = fmaxf(v1, 0.f);
                v2 = fmaxf(v2, 0.f); v3 = fmaxf(v3, 0.f);
            } else {
                v0 = tanhf(v0); v1 = tanhf(v1); v2 = tanhf(v2); v3 = tanhf(v3);
            }
            if (c0 >= N) { v0 = 0.f; v2 = 0.f; }
            if (c1 >= N) { v1 = 0.f; v3 = 0.f; }
            acc[mi][ni][0] = v0; acc[mi][ni][1] = v1;
            acc[mi][ni][2] = v2; acc[mi][ni][3] = v3;
            s[mi][0] += v0 + v1; q[mi][0] += v0 * v0 + v1 * v1;
            s[mi][1] += v2 + v3; q[mi][1] += v2 * v2 + v3 * v3;
        }
#pragma unroll
    for (int off = 1; off <= 2; off <<= 1)
#pragma unroll
        for (int mi = 0; mi < 2; mi++)
#pragma unroll
            for (int dr = 0; dr < 2; dr++) {
                s[mi][dr] += __shfl_xor_sync(0xffffffffu, s[mi][dr], off);
                q[mi][dr] += __shfl_xor_sync(0xffffffffu, q[mi][dr], off);
            }
    if (tq == 0) {
#pragma unroll
        for (int mi = 0; mi < 2; mi++)
#pragma unroll
            for (int dr = 0; dr < 2; dr++) {
                int r = wm * 32 + mi * 16 + g + 8 * dr;
                redS[r * NWN + wn] = s[mi][dr];
                redQ[r * NWN + wn] = q[mi][dr];
            }
    }
    __syncthreads();

    float mu[2][2], rs[2][2];
    const float invN = 1.f / (float)N;
#pragma unroll
    for (int mi = 0; mi < 2; mi++)
#pragma unroll
        for (int dr = 0; dr < 2; dr++) {
            int r = wm * 32 + mi * 16 + g + 8 * dr;
            float ss = 0.f, qq = 0.f;
#pragma unroll
            for (int x = 0; x < NWN; x++) { ss += redS[r * NWN + x]; qq += redQ[r * NWN + x]; }
            mu[mi][dr] = ss * invN;
            rs[mi][dr] = rsqrtf(qq * invN - mu[mi][dr] * mu[mi][dr] + 1e-5f);
        }

    if (EPI == 1) {
#pragma unroll
        for (int mi = 0; mi < 2; mi++) {
            int gr0 = row0 + wm * 32 + mi * 16 + g;
#pragma unroll
            for (int ni = 0; ni < 8; ni++) {
                int c0 = wn * 64 + ni * 8 + tq * 2, c1 = c0 + 1;
                float g0 = (c0 < N) ? gamma[c0] : 0.f, g1 = (c1 < N) ? gamma[c1] : 0.f;
                float t0 = (c0 < N) ? beta[c0] : 0.f,  t1 = (c1 < N) ? beta[c1] : 0.f;
#pragma unroll
                for (int dr = 0; dr < 2; dr++) {
                    int gr = gr0 + 8 * dr;
                    float w0 = (c0 < N) ? (acc[mi][ni][2 * dr + 0] - mu[mi][dr]) * rs[mi][dr] * g0 + t0 : 0.f;
                    float w1 = (c1 < N) ? (acc[mi][ni][2 * dr + 1] - mu[mi][dr]) * rs[mi][dr] * g1 + t1 : 0.f;
                    __nv_bfloat16 h0 = __float2bfloat16(w0), h1 = __float2bfloat16(w1);
                    __nv_bfloat16 l0 = __float2bfloat16(w0 - __bfloat162float(h0));
                    __nv_bfloat16 l1 = __float2bfloat16(w1 - __bfloat162float(h1));
                    *(__nv_bfloat162*)(Chi + (size_t)gr * 256 + c0) = __halves2bfloat162(h0, h1);
                    *(__nv_bfloat162*)(Clo + (size_t)gr * 256 + c0) = __halves2bfloat162(l0, l1);
                }
            }
        }
    } else { // EPI == 2
        float d[2][2] = {{0, 0}, {0, 0}};
#pragma unroll
        for (int mi = 0; mi < 2; mi++)
#pragma unroll
            for (int ni = 0; ni < 8; ni++) {
                int c0 = wn * 64 + ni * 8 + tq * 2, c1 = c0 + 1;
#pragma unroll
                for (int dr = 0; dr < 2; dr++) {
                    if (c0 < N)
                        d[mi][dr] += ((acc[mi][ni][2 * dr + 0] - mu[mi][dr]) * rs[mi][dr] * gamma[c0] + beta[c0]) * W2[c0];
                    if (c1 < N)
                        d[mi][dr] += ((acc[mi][ni][2 * dr + 1] - mu[mi][dr]) * rs[mi][dr] * gamma[c1] + beta[c1]) * W2[c1];
                }
            }
#pragma unroll
        for (int off = 1; off <= 2; off <<= 1)
#pragma unroll
            for (int mi = 0; mi < 2; mi++)
#pragma unroll
                for (int dr = 0; dr < 2; dr++)
                    d[mi][dr] += __shfl_xor_sync(0xffffffffu, d[mi][dr], off);
        __syncthreads();  // redS reuse
        if (tq == 0) {
#pragma unroll
            for (int mi = 0; mi < 2; mi++)
#pragma unroll
                for (int dr = 0; dr < 2; dr++) {
                    int r = wm * 32 + mi * 16 + g + 8 * dr;
                    redS[r * NWN + wn] = d[mi][dr];
                }
        }
        __syncthreads();
        if (wn == 0 && tq == 0) {
            float bb = b2[0];
#pragma unroll
            for (int mi = 0; mi < 2; mi++)
#pragma unroll
                for (int dr = 0; dr < 2; dr++) {
                    int r = wm * 32 + mi * 16 + g + 8 * dr;
                    float dd = 0.f;
#pragma unroll
                    for (int x = 0; x < NWN; x++) dd += redS[r * NWN + x];
                    Cf[row0 + r] = 1.f / (1.f + expf(-(dd + bb)));
                }
        }
    }
}

// ---------------- core combine: core[b,i,j] = LN(relu(U[b,i] + V[b,j] + bias)) ----------------
// UV layout: [16384][512] fp32, cols 0..255 = U (top-half product), 256..511 = V (bottom-half)
__global__ void __launch_bounds__(256) combine_core(
    const float* __restrict__ UV, const float* __restrict__ bias,
    const float* __restrict__ gamma, const float* __restrict__ beta,
    __nv_bfloat16* __restrict__ ch, __nv_bfloat16* __restrict__ cl)
{
    const int r    = blockIdx.x * 8 + (threadIdx.x >> 5);  // pair-row id
    const int lane = threadIdx.x & 31;
    const int b = r / 56, rem = r - b * 56;
    const int i = rem / 7, jj = rem - i * 7;
    const int j = jj + (jj >= i ? 1 : 0);
    const float4* up = (const float4*)(UV + (size_t)(b * 8 + i) * 512);
    const float4* vp = (const float4*)(UV + (size_t)(b * 8 + j) * 512 + 256);

    const int c0 = lane * 8;
    float v[8];
#pragma unroll
    for (int h = 0; h < 2; h++) {
        float4 u4 = up[lane * 2 + h];
        float4 v4 = vp[lane * 2 + h];
        float* vv = v + h * 4;
        vv[0] = u4.x + v4.x; vv[1] = u4.y + v4.y;
        vv[2] = u4.z + v4.z; vv[3] = u4.w + v4.w;
    }
    float s = 0.f, q = 0.f;
#pragma unroll
    for (int e = 0; e < 8; e++) {
        int c = c0 + e;
        float x = (c < 250) ? fmaxf(v[e] + bias[c], 0.f) : 0.f;
        v[e] = x;
        s += x; q += x * x;
    }
#pragma unroll
    for (int off = 16; off > 0; off >>= 1) {
        s += __shfl_xor_sync(0xffffffffu, s, off);
        q += __shfl_xor_sync(0xffffffffu, q, off);
    }
    const float invN = 1.f / 250.f;
    float mu = s * invN;
    float rs = rsqrtf(q * invN - mu * mu + 1e-5f);

    uint4 hw, lw;
    __nv_bfloat16* hp = (__nv_bfloat16*)&hw;
    __nv_bfloat16* lp = (__nv_bfloat16*)&lw;
#pragma unroll
    for (int e = 0; e < 8; e++) {
        int c = c0 + e;
        float w = (c < 250) ? (v[e] - mu) * rs * gamma[c] + beta[c] : 0.f;
        __nv_bfloat16 h = __float2bfloat16(w);
        hp[e] = h;
        lp[e] = __float2bfloat16(w - __bfloat162float(h));
    }
    *(uint4*)(ch + (size_t)r * 256 + c0) = hw;
    *(uint4*)(cl + (size_t)r * 256 + c0) = lw;
}

// effect: eff[bk][c] = sum_j (ctx_hi+ctx_lo)[bk*7+j][c] * att[bk*7+j], stored hi/lo
__global__ void effect3(const __nv_bfloat16* __restrict__ ch, const __nv_bfloat16* __restrict__ cl,
                        const float* __restrict__ att,
                        __nv_bfloat16* __restrict__ eh, __nv_bfloat16* __restrict__ el)
{
    int bk = blockIdx.x, c = threadIdx.x;
    __shared__ float a[7];
    if (c < 7) a[c] = att[bk * 7 + c];
    __syncthreads();
    size_t base = (size_t)bk * 7 * 256 + c;
    float s = 0.f;
#pragma unroll
    for (int j = 0; j < 7; j++)
        s = fmaf(__bfloat162float(ch[base + j * 256]) + __bfloat162float(cl[base + j * 256]),
                 a[j], s);
    __nv_bfloat16 h = __float2bfloat16(s);
    eh[(size_t)bk * 256 + c] = h;
    el[(size_t)bk * 256 + c] = __float2bfloat16(s - __bfloat162float(h));
}

extern "C" void kernel_launch(void* const* d_in, const int* in_sizes, int n_in,
                              void* d_out, int out_size)
{
    const float* x       = (const float*)d_in[0];
    const float* state   = (const float*)d_in[1];
    const float* enc_W   = (const float*)d_in[2];
    const float* enc_b   = (const float*)d_in[3];
    const float* enc_g   = (const float*)d_in[4];
    const float* enc_bt  = (const float*)d_in[5];
    const float* core_W  = (const float*)d_in[6];
    const float* core_b  = (const float*)d_in[7];
    const float* core_g  = (const float*)d_in[8];
    const float* core_bt = (const float*)d_in[9];
    const float* ctx_W   = (const float*)d_in[10];
    const float* ctx_b   = (const float*)d_in[11];
    const float* ctx_g   = (const float*)d_in[12];
    const float* ctx_bt  = (const float*)d_in[13];
    const float* att_W1  = (const float*)d_in[14];
    const float* att_b1  = (const float*)d_in[15];
    const float* att_g   = (const float*)d_in[16];
    const float* att_bt  = (const float*)d_in[17];
    const float* att_W2  = (const float*)d_in[18];
    const float* att_b2  = (const float*)d_in[19];
    const float* out_W   = (const float*)d_in[20];
    const float* out_b   = (const float*)d_in[21];
    float* out = (float*)d_out;

    __nv_bfloat16 *sp_h, *sp_l, *xp_h, *xp_l, *s1_h, *s1_l, *co_h, *co_l, *cx_h, *cx_l;
    __nv_bfloat16 *ef_h, *ef_l, *eW, *uvW, *xW, *aW, *oW;
    float *att, *uv;
    cudaGetSymbolAddress((void**)&sp_h, g_sp_h); cudaGetSymbolAddress((void**)&sp_l, g_sp_l);
    cudaGetSymbolAddress((void**)&xp_h, g_xp_h); cudaGetSymbolAddress((void**)&xp_l, g_xp_l);
    cudaGetSymbolAddress((void**)&s1_h, g_s1_h); cudaGetSymbolAddress((void**)&s1_l, g_s1_l);
    cudaGetSymbolAddress((void**)&co_h, g_co_h); cudaGetSymbolAddress((void**)&co_l, g_co_l);
    cudaGetSymbolAddress((void**)&cx_h, g_cx_h); cudaGetSymbolAddress((void**)&cx_l, g_cx_l);
    cudaGetSymbolAddress((void**)&ef_h, g_ef_h); cudaGetSymbolAddress((void**)&ef_l, g_ef_l);
    cudaGetSymbolAddress((void**)&eW, g_eW);     cudaGetSymbolAddress((void**)&uvW, g_uvW);
    cudaGetSymbolAddress((void**)&xW, g_xW);     cudaGetSymbolAddress((void**)&aW, g_aW);
    cudaGetSymbolAddress((void**)&oW, g_oW);     cudaGetSymbolAddress((void**)&att, g_att);
    cudaGetSymbolAddress((void**)&uv, g_uv);

    const int SM_STD = 2 * (64 + 256) * 72 * 2 + 64 * 4 * 2 * 4;    // 94208
    const int SM_ATT = 2 * (128 + 128) * 72 * 2 + 128 * 2 * 2 * 4;  // 75776
    cudaFuncSetAttribute((const void*)hgemm<64, 256, 768, 0, 1>,  cudaFuncAttributeMaxDynamicSharedMemorySize, SM_STD);
    cudaFuncSetAttribute((const void*)hgemm<64, 256, 768, 0, 0>,  cudaFuncAttributeMaxDynamicSharedMemorySize, SM_STD);
    cudaFuncSetAttribute((const void*)hgemm<128, 128, 768, 0, 2>, cudaFuncAttributeMaxDynamicSharedMemorySize, SM_ATT);
    cudaFuncSetAttribute((const void*)hgemm<64, 256, 3264, 2, 0>, cudaFuncAttributeMaxDynamicSharedMemorySize, SM_STD);

    // prep
    cvt_pad<<<(16384 * 256) / 256, 256>>>(sp_h, sp_l, 256, state, 250, 16384);
    cvt_pad<<<(16384 * 576) / 256, 256>>>(xp_h, xp_l, 576, x, 576, 16384);
    prep_w<<<(256 * 768) / 256, 256>>>(eW, 768, 256, 256, enc_W, 250, 0, 250, 0, 0, 0, 0);
    prep_w<<<(256 * 768) / 256, 256>>>(uvW,             768, 256, 256, core_W, 250, 0,   250, 0, 0, 0, 0);
    prep_w<<<(256 * 768) / 256, 256>>>(uvW + 256 * 768, 768, 256, 256, core_W, 250, 250, 250, 0, 0, 0, 0);
    prep_w<<<(256 * 768) / 256, 256>>>(xW, 768, 256, 256, ctx_W, 250, 0, 250, 0, 0, 0, 0);
    prep_w<<<(128 * 768) / 256, 256>>>(aW, 768, 256, 128, att_W1, 100, 0, 250, 0, 0, 0, 0);
    prep_w<<<(256 * 3264) / 256, 256>>>(oW, 3264, 1088, 256, out_W, 250, 0, 250, 250, 250, 500, 576);

    // 1. enc: s1 = LN(relu(state @ enc_W + b))
    hgemm<64, 256, 768, 0, 1><<<BKTOT / 64, 256, SM_STD>>>(
        sp_h, sp_l, nullptr, nullptr, nullptr, nullptr, eW,
        enc_b, enc_g, enc_bt, nullptr, nullptr,
        nullptr, s1_h, s1_l, 250, 0);
    // 2. UV = s1 @ [W_top ++ W_bot]  (fp32, no epilogue; N-tiled via grid.y)
    hgemm<64, 256, 768, 0, 0><<<dim3(BKTOT / 64, 2), 256, SM_STD>>>(
        s1_h, s1_l, nullptr, nullptr, nullptr, nullptr, uvW,
        nullptr, nullptr, nullptr, nullptr, nullptr,
        uv, nullptr, nullptr, 256, 512);
    // 3. core[b,i,j] = LN(relu(U[b,i] + V[b,j] + core_b))  (bandwidth-bound)
    combine_core<<<RR / 8, 256>>>(uv, core_b, core_g, core_bt, co_h, co_l);
    // 4. ctx
    hgemm<64, 256, 768, 0, 1><<<RR / 64, 256, SM_STD>>>(
        co_h, co_l, nullptr, nullptr, nullptr, nullptr, xW,
        ctx_b, ctx_g, ctx_bt, nullptr, nullptr,
        nullptr, cx_h, cx_l, 250, 0);
    // 5. att scores
    hgemm<128, 128, 768, 0, 2><<<RR / 128, 256, SM_ATT>>>(
        co_h, co_l, nullptr, nullptr, nullptr, nullptr, aW,
        att_b1, att_g, att_bt, att_W2, att_b2,
        att, nullptr, nullptr, 100, 0);
    // 6. attention-weighted reduction
    effect3<<<BKTOT, 256>>>(cx_h, cx_l, att, ef_h, ef_l);
    // 7. out: [s1 | eff | x] @ out_W + b
    hgemm<64, 256, 3264, 2, 0><<<BKTOT / 64, 256, SM_STD>>>(
        s1_h, s1_l, ef_h, ef_l, xp_h, xp_l, oW,
        out_b, nullptr, nullptr, nullptr, nullptr,
        out, nullptr, nullptr, 250, 250);
}